// round 3
// baseline (speedup 1.0000x reference)
#include <cuda_runtime.h>
#include <cuda_bf16.h>
#include <math.h>

// ---------------------------------------------------------------------------
// Problem constants (fixed shapes from the reference)
// ---------------------------------------------------------------------------
#define BB   4
#define SS   2048
#define DD   1024
#define FF   4096
#define HH   16
#define DH   64
#define MM   (BB * SS)          // 8192 rows
#define EPS  1e-6f
#define THRESH 0.15f

// ---------------------------------------------------------------------------
// Scratch buffers (device globals; no allocations allowed)
// ---------------------------------------------------------------------------
__device__ float g_X2[MM * DD];   // ln1 output
__device__ float g_Q [MM * DD];
__device__ float g_K [MM * DD];
__device__ float g_V [MM * DD];
__device__ float g_AT[MM * DD];   // attention output
__device__ float g_XR[MM * DD];   // x + attn (residual carried to the end)
__device__ float g_Y [MM * DD];   // ln2 + threshold output
__device__ float g_H [MM * FF];   // ffn hidden

// ---------------------------------------------------------------------------
// Block-wide sum reduction (256 threads, 8 warps)
// ---------------------------------------------------------------------------
__device__ __forceinline__ float block_reduce_sum(float v, float* sbuf) {
    int lane = threadIdx.x & 31;
    int warp = threadIdx.x >> 5;
    #pragma unroll
    for (int o = 16; o > 0; o >>= 1) v += __shfl_down_sync(0xffffffffu, v, o);
    if (lane == 0) sbuf[warp] = v;
    __syncthreads();
    if (warp == 0) {
        float t = (lane < 8) ? sbuf[lane] : 0.0f;
        #pragma unroll
        for (int o = 4; o > 0; o >>= 1) t += __shfl_down_sync(0xffffffffu, t, o);
        if (lane == 0) sbuf[0] = t;
    }
    __syncthreads();
    float r = sbuf[0];
    __syncthreads();          // allow sbuf reuse
    return r;
}

// ---------------------------------------------------------------------------
// LayerNorm (torch-style: unbiased std, eps added to std), optional:
//   - add a second input (residual) before the norm
//   - store the pre-norm sum (xr)
//   - threshold mask (val < 0.15 -> 0)
// One block per row (D = 1024, 256 threads, 4 floats/thread).
// ---------------------------------------------------------------------------
__global__ __launch_bounds__(256)
void ln_kernel(const float* __restrict__ x,
               const float* __restrict__ add,     // may be null
               const float* __restrict__ alpha,
               const float* __restrict__ bias,
               float* __restrict__ xr,            // may be null
               float* __restrict__ out,
               int applyThresh)
{
    __shared__ float sbuf[8];
    const int row = blockIdx.x;
    const int c4  = threadIdx.x * 4;
    const size_t base = (size_t)row * DD;

    float4 v = *(const float4*)(x + base + c4);
    if (add) {
        float4 a = *(const float4*)(add + base + c4);
        v.x += a.x; v.y += a.y; v.z += a.z; v.w += a.w;
    }
    if (xr) *(float4*)(xr + base + c4) = v;

    float s = v.x + v.y + v.z + v.w;
    s = block_reduce_sum(s, sbuf);
    const float mu = s * (1.0f / (float)DD);

    float dx0 = v.x - mu, dx1 = v.y - mu, dx2 = v.z - mu, dx3 = v.w - mu;
    float s2 = dx0*dx0 + dx1*dx1 + dx2*dx2 + dx3*dx3;
    s2 = block_reduce_sum(s2, sbuf);

    const float sd   = sqrtf(s2 * (1.0f / (float)(DD - 1)));
    const float rinv = 1.0f / (sd + EPS);

    float4 al = *(const float4*)(alpha + c4);
    float4 bi = *(const float4*)(bias  + c4);

    float4 o;
    o.x = al.x * dx0 * rinv + bi.x;
    o.y = al.y * dx1 * rinv + bi.y;
    o.z = al.z * dx2 * rinv + bi.z;
    o.w = al.w * dx3 * rinv + bi.w;
    if (applyThresh) {
        if (o.x < THRESH) o.x = 0.0f;
        if (o.y < THRESH) o.y = 0.0f;
        if (o.z < THRESH) o.z = 0.0f;
        if (o.w < THRESH) o.w = 0.0f;
    }
    *(float4*)(out + base + c4) = o;
}

// ---------------------------------------------------------------------------
// SGEMM: C[M,N] = A[M,K] @ W[N,K]^T + bias, optional relu / residual add.
// 128x128 tile, BK=16, 256 threads, 8x8 per-thread micro-tile.
// Double-buffered SMEM (one barrier per K-iteration) +
// global->register prefetch of the next K-tile.
// M, N divisible by 128; K divisible by 16 (holds for all call sites).
// ---------------------------------------------------------------------------
__global__ __launch_bounds__(256)
void gemm_kernel(const float* __restrict__ A,
                 const float* __restrict__ W,
                 const float* __restrict__ bias,
                 const float* __restrict__ res,   // may be null
                 float* __restrict__ C,
                 int M, int N, int K, int doRelu)
{
    __shared__ __align__(16) float As[2][16][128];
    __shared__ __align__(16) float Bs[2][16][128];

    const int tid = threadIdx.x;
    const int m0 = blockIdx.y * 128;
    const int n0 = blockIdx.x * 128;
    const int ty = tid >> 4;          // 0..15
    const int tx = tid & 15;          // 0..15

    // loader mapping: 512 float4 per operand tile; this thread owns f0, f1
    const int f0 = tid, f1 = tid + 256;
    const int ar0 = f0 >> 2, ac0 = (f0 & 3) << 2;
    const int ar1 = f1 >> 2, ac1 = (f1 & 3) << 2;

    const float* Ab = A + (size_t)m0 * K;
    const float* Wb = W + (size_t)n0 * K;

    float acc[8][8];
    #pragma unroll
    for (int i = 0; i < 8; ++i)
        #pragma unroll
        for (int j = 0; j < 8; ++j) acc[i][j] = 0.0f;

    // first tile: global -> smem buffer 0
    {
        float4 a0 = *(const float4*)(Ab + (size_t)ar0 * K + ac0);
        float4 a1 = *(const float4*)(Ab + (size_t)ar1 * K + ac1);
        float4 b0 = *(const float4*)(Wb + (size_t)ar0 * K + ac0);
        float4 b1 = *(const float4*)(Wb + (size_t)ar1 * K + ac1);
        As[0][ac0+0][ar0] = a0.x; As[0][ac0+1][ar0] = a0.y; As[0][ac0+2][ar0] = a0.z; As[0][ac0+3][ar0] = a0.w;
        As[0][ac1+0][ar1] = a1.x; As[0][ac1+1][ar1] = a1.y; As[0][ac1+2][ar1] = a1.z; As[0][ac1+3][ar1] = a1.w;
        Bs[0][ac0+0][ar0] = b0.x; Bs[0][ac0+1][ar0] = b0.y; Bs[0][ac0+2][ar0] = b0.z; Bs[0][ac0+3][ar0] = b0.w;
        Bs[0][ac1+0][ar1] = b1.x; Bs[0][ac1+1][ar1] = b1.y; Bs[0][ac1+2][ar1] = b1.z; Bs[0][ac1+3][ar1] = b1.w;
    }
    __syncthreads();

    const int nt = K >> 4;
    for (int t = 0; t < nt; ++t) {
        const int cur = t & 1;
        const int nxt = cur ^ 1;
        float4 na0, na1, nb0, nb1;
        const bool has = (t + 1 < nt);
        if (has) {
            const int k0 = (t + 1) << 4;
            na0 = *(const float4*)(Ab + (size_t)ar0 * K + k0 + ac0);
            na1 = *(const float4*)(Ab + (size_t)ar1 * K + k0 + ac1);
            nb0 = *(const float4*)(Wb + (size_t)ar0 * K + k0 + ac0);
            nb1 = *(const float4*)(Wb + (size_t)ar1 * K + k0 + ac1);
        }
        #pragma unroll
        for (int kk = 0; kk < 16; ++kk) {
            float4 av0 = *(const float4*)&As[cur][kk][ty * 8];
            float4 av1 = *(const float4*)&As[cur][kk][ty * 8 + 4];
            float4 bv0 = *(const float4*)&Bs[cur][kk][tx * 8];
            float4 bv1 = *(const float4*)&Bs[cur][kk][tx * 8 + 4];
            float a[8] = {av0.x, av0.y, av0.z, av0.w, av1.x, av1.y, av1.z, av1.w};
            float b[8] = {bv0.x, bv0.y, bv0.z, bv0.w, bv1.x, bv1.y, bv1.z, bv1.w};
            #pragma unroll
            for (int i = 0; i < 8; ++i)
                #pragma unroll
                for (int j = 0; j < 8; ++j)
                    acc[i][j] = fmaf(a[i], b[j], acc[i][j]);
        }
        if (has) {
            // Write next tile into the other buffer. Safe without a pre-store
            // barrier: the barrier at the end of iteration t-1 guarantees no
            // thread is still reading buffer `nxt`.
            As[nxt][ac0+0][ar0] = na0.x; As[nxt][ac0+1][ar0] = na0.y; As[nxt][ac0+2][ar0] = na0.z; As[nxt][ac0+3][ar0] = na0.w;
            As[nxt][ac1+0][ar1] = na1.x; As[nxt][ac1+1][ar1] = na1.y; As[nxt][ac1+2][ar1] = na1.z; As[nxt][ac1+3][ar1] = na1.w;
            Bs[nxt][ac0+0][ar0] = nb0.x; Bs[nxt][ac0+1][ar0] = nb0.y; Bs[nxt][ac0+2][ar0] = nb0.z; Bs[nxt][ac0+3][ar0] = nb0.w;
            Bs[nxt][ac1+0][ar1] = nb1.x; Bs[nxt][ac1+1][ar1] = nb1.y; Bs[nxt][ac1+2][ar1] = nb1.z; Bs[nxt][ac1+3][ar1] = nb1.w;
            __syncthreads();
        }
    }

    // epilogue
    float bv[8];
    #pragma unroll
    for (int j = 0; j < 8; ++j) bv[j] = bias[n0 + tx * 8 + j];

    #pragma unroll
    for (int i = 0; i < 8; ++i) {
        const int m = m0 + ty * 8 + i;
        const size_t off = (size_t)m * N + n0 + tx * 8;
        float o[8];
        #pragma unroll
        for (int j = 0; j < 8; ++j) {
            float v = acc[i][j] + bv[j];
            if (doRelu) v = fmaxf(v, 0.0f);
            o[j] = v;
        }
        if (res) {
            float4 r0 = *(const float4*)(res + off);
            float4 r1 = *(const float4*)(res + off + 4);
            o[0] += r0.x; o[1] += r0.y; o[2] += r0.z; o[3] += r0.w;
            o[4] += r1.x; o[5] += r1.y; o[6] += r1.z; o[7] += r1.w;
        }
        *(float4*)(C + off)     = make_float4(o[0], o[1], o[2], o[3]);
        *(float4*)(C + off + 4) = make_float4(o[4], o[5], o[6], o[7]);
    }
}

// ---------------------------------------------------------------------------
// Flash attention, fp32. One block = one (b, h, 64-query tile).
// 128 threads, K/V tiles of 64 rows, online softmax.
// Per-thread micro-tile: 4 q-rows x 8 k-cols (k-cols STRIDED by 8 so that
// the 8 concurrent lanes of each smem phase read CONSECUTIVE K rows ->
// conflict-free LDS.128 with the 68-float K row stride).
// Dynamic smem: Qs[64][64] | Ks[64][68] | Vs[64][64] | Ps[64][64] = 65 KB.
// Q/K/V layout: [B, S, H*DH] with head offset h*64.
// ---------------------------------------------------------------------------
#define ATTN_SMEM_BYTES ((64*64 + 64*68 + 64*64 + 64*64) * 4)

__global__ __launch_bounds__(128)
void attn_kernel(const float* __restrict__ Qg,
                 const float* __restrict__ Kg,
                 const float* __restrict__ Vg,
                 float* __restrict__ Og)
{
    extern __shared__ float sm[];
    float (*Qs)[64] = (float(*)[64])(sm);
    float (*Ks)[68] = (float(*)[68])(sm + 64*64);
    float (*Vs)[64] = (float(*)[64])(sm + 64*64 + 64*68);
    float (*Ps)[64] = (float(*)[64])(sm + 64*64 + 64*68 + 64*64);

    const int qt = blockIdx.x;   // 0..31
    const int h  = blockIdx.y;   // 0..15
    const int b  = blockIdx.z;   // 0..3
    const int tid = threadIdx.x;
    const int tq = tid >> 3;     // 0..15  (q rows tq*4 .. tq*4+3)
    const int tk = tid & 7;      // 0..7   (QK: k cols tk+8j; PV: d cols tk*8+j)
    const float scale = 0.125f;  // 1/sqrt(64)

    // load Q tile (64 x 64) — row-major, 16B-aligned rows (stride 64 floats)
    {
        const float* qbase = Qg + ((size_t)(b * SS + qt * 64)) * DD + h * DH;
        for (int f = tid; f < 1024; f += 128) {
            const int r = f >> 4, c = (f & 15) << 2;
            *(float4*)&Qs[r][c] = *(const float4*)(qbase + (size_t)r * DD + c);
        }
    }

    float m[4], l[4], acc[4][8];
    #pragma unroll
    for (int i = 0; i < 4; ++i) {
        m[i] = -1e30f; l[i] = 0.0f;
        #pragma unroll
        for (int j = 0; j < 8; ++j) acc[i][j] = 0.0f;
    }

    for (int kt = 0; kt < SS / 64; ++kt) {
        __syncthreads();   // previous iteration done reading Ks/Vs
        {
            const float* kbase = Kg + ((size_t)(b * SS + kt * 64)) * DD + h * DH;
            const float* vbase = Vg + ((size_t)(b * SS + kt * 64)) * DD + h * DH;
            for (int f = tid; f < 1024; f += 128) {
                const int r = f >> 4, c = (f & 15) << 2;
                *(float4*)&Ks[r][c] = *(const float4*)(kbase + (size_t)r * DD + c);
                *(float4*)&Vs[r][c] = *(const float4*)(vbase + (size_t)r * DD + c);
            }
        }
        __syncthreads();

        // S = Q K^T : this thread -> 4 q rows x 8 strided k cols (tk + 8j)
        float s[4][8];
        #pragma unroll
        for (int i = 0; i < 4; ++i)
            #pragma unroll
            for (int j = 0; j < 8; ++j) s[i][j] = 0.0f;

        #pragma unroll 2
        for (int d = 0; d < DH; d += 4) {
            float4 qa[4], kb[8];
            #pragma unroll
            for (int i = 0; i < 4; ++i) qa[i] = *(const float4*)&Qs[tq * 4 + i][d];
            #pragma unroll
            for (int j = 0; j < 8; ++j) kb[j] = *(const float4*)&Ks[tk + 8 * j][d];
            #pragma unroll
            for (int i = 0; i < 4; ++i)
                #pragma unroll
                for (int j = 0; j < 8; ++j) {
                    s[i][j] = fmaf(qa[i].x, kb[j].x, s[i][j]);
                    s[i][j] = fmaf(qa[i].y, kb[j].y, s[i][j]);
                    s[i][j] = fmaf(qa[i].z, kb[j].z, s[i][j]);
                    s[i][j] = fmaf(qa[i].w, kb[j].w, s[i][j]);
                }
        }

        // online softmax per q-row (8-thread groups share a row)
        #pragma unroll
        for (int i = 0; i < 4; ++i) {
            float rm = -1e30f;
            #pragma unroll
            for (int j = 0; j < 8; ++j) { s[i][j] *= scale; rm = fmaxf(rm, s[i][j]); }
            #pragma unroll
            for (int o = 1; o < 8; o <<= 1)
                rm = fmaxf(rm, __shfl_xor_sync(0xffffffffu, rm, o));
            const float mn   = fmaxf(m[i], rm);
            const float corr = __expf(m[i] - mn);
            float rs = 0.0f;
            #pragma unroll
            for (int j = 0; j < 8; ++j) {
                const float p = __expf(s[i][j] - mn);
                Ps[tq * 4 + i][tk + 8 * j] = p;   // lanes hit distinct banks
                rs += p;
            }
            #pragma unroll
            for (int o = 1; o < 8; o <<= 1)
                rs += __shfl_xor_sync(0xffffffffu, rs, o);
            l[i] = l[i] * corr + rs;
            m[i] = mn;
            #pragma unroll
            for (int j = 0; j < 8; ++j) acc[i][j] *= corr;
        }
        // P rows tq*4+i are written and read entirely within this warp's
        // tq-groups -> warp sync is sufficient before the PV pass.
        __syncwarp();

        // acc += P @ V : this thread -> 4 q rows x 8 contiguous d cols (tk*8+j)
        #pragma unroll 4
        for (int k = 0; k < 64; ++k) {
            float4 v0 = *(const float4*)&Vs[k][tk * 8];
            float4 v1 = *(const float4*)&Vs[k][tk * 8 + 4];
            float pv[4];
            #pragma unroll
            for (int i = 0; i < 4; ++i) pv[i] = Ps[tq * 4 + i][k];
            #pragma unroll
            for (int i = 0; i < 4; ++i) {
                acc[i][0] = fmaf(pv[i], v0.x, acc[i][0]);
                acc[i][1] = fmaf(pv[i], v0.y, acc[i][1]);
                acc[i][2] = fmaf(pv[i], v0.z, acc[i][2]);
                acc[i][3] = fmaf(pv[i], v0.w, acc[i][3]);
                acc[i][4] = fmaf(pv[i], v1.x, acc[i][4]);
                acc[i][5] = fmaf(pv[i], v1.y, acc[i][5]);
                acc[i][6] = fmaf(pv[i], v1.z, acc[i][6]);
                acc[i][7] = fmaf(pv[i], v1.w, acc[i][7]);
            }
        }
    }

    // epilogue: normalize and store
    #pragma unroll
    for (int i = 0; i < 4; ++i) {
        const float inv = 1.0f / l[i];
        const size_t row = (size_t)(b * SS + qt * 64 + tq * 4 + i);
        float* ob = Og + row * DD + h * DH + tk * 8;
        *(float4*)(ob)     = make_float4(acc[i][0]*inv, acc[i][1]*inv, acc[i][2]*inv, acc[i][3]*inv);
        *(float4*)(ob + 4) = make_float4(acc[i][4]*inv, acc[i][5]*inv, acc[i][6]*inv, acc[i][7]*inv);
    }
}

// ---------------------------------------------------------------------------
// Launch
// ---------------------------------------------------------------------------
extern "C" void kernel_launch(void* const* d_in, const int* in_sizes, int n_in,
                              void* d_out, int out_size)
{
    const float* x      = (const float*)d_in[0];
    const float* alpha1 = (const float*)d_in[1];
    const float* bias1  = (const float*)d_in[2];
    const float* alpha2 = (const float*)d_in[3];
    const float* bias2  = (const float*)d_in[4];
    const float* wq     = (const float*)d_in[5];
    const float* bq     = (const float*)d_in[6];
    const float* wk     = (const float*)d_in[7];
    const float* bk     = (const float*)d_in[8];
    const float* wv     = (const float*)d_in[9];
    const float* bv     = (const float*)d_in[10];
    const float* w1     = (const float*)d_in[11];
    const float* b1     = (const float*)d_in[12];
    const float* w2     = (const float*)d_in[13];
    const float* b2     = (const float*)d_in[14];
    float* out = (float*)d_out;

    float *X2, *Qb, *Kb, *Vb, *AT, *XR, *Y, *Hb;
    cudaGetSymbolAddress((void**)&X2, g_X2);
    cudaGetSymbolAddress((void**)&Qb, g_Q);
    cudaGetSymbolAddress((void**)&Kb, g_K);
    cudaGetSymbolAddress((void**)&Vb, g_V);
    cudaGetSymbolAddress((void**)&AT, g_AT);
    cudaGetSymbolAddress((void**)&XR, g_XR);
    cudaGetSymbolAddress((void**)&Y,  g_Y);
    cudaGetSymbolAddress((void**)&Hb, g_H);

    // allow 65 KB dynamic smem for the attention kernel (idempotent)
    cudaFuncSetAttribute(attn_kernel,
                         cudaFuncAttributeMaxDynamicSharedMemorySize,
                         ATTN_SMEM_BYTES);

    // 1. pre-norm 1
    ln_kernel<<<MM, 256>>>(x, nullptr, alpha1, bias1, nullptr, X2, 0);

    // 2-4. Q, K, V projections
    dim3 gqkv(DD / 128, MM / 128);
    gemm_kernel<<<gqkv, 256>>>(X2, wq, bq, nullptr, Qb, MM, DD, DD, 0);
    gemm_kernel<<<gqkv, 256>>>(X2, wk, bk, nullptr, Kb, MM, DD, DD, 0);
    gemm_kernel<<<gqkv, 256>>>(X2, wv, bv, nullptr, Vb, MM, DD, DD, 0);

    // 5. attention
    attn_kernel<<<dim3(SS / 64, HH, BB), 128, ATTN_SMEM_BYTES>>>(Qb, Kb, Vb, AT);

    // 6. residual + norm 2 + threshold (stores XR = x + attn, Y = masked norm)
    ln_kernel<<<MM, 256>>>(x, AT, alpha2, bias2, XR, Y, 1);

    // 7. FFN
    gemm_kernel<<<dim3(FF / 128, MM / 128), 256>>>(Y,  w1, b1, nullptr, Hb, MM, FF, DD, 1);
    gemm_kernel<<<dim3(DD / 128, MM / 128), 256>>>(Hb, w2, b2, XR,      out, MM, DD, FF, 0);
}

// round 9
// speedup vs baseline: 1.7205x; 1.7205x over previous
#include <cuda_runtime.h>
#include <cuda_bf16.h>
#include <math.h>
#include <stdint.h>

// ---------------------------------------------------------------------------
// Problem constants
// ---------------------------------------------------------------------------
#define BB   4
#define SS   2048
#define DD   1024
#define FF   4096
#define HH   16
#define DH   64
#define MM   (BB * SS)          // 8192 rows
#define EPS  1e-6f
#define THRESH 0.15f

// ---------------------------------------------------------------------------
// Scratch buffers (device globals; no allocations allowed)
// ---------------------------------------------------------------------------
// fp32
__device__ float g_Q [MM * DD];
__device__ float g_K [MM * DD];
__device__ float g_V [MM * DD];
__device__ float g_AT[MM * DD];
__device__ float g_XR[MM * DD];
// bf16 hi/lo activations
__device__ __nv_bfloat16 g_X2h[MM * DD], g_X2l[MM * DD];
__device__ __nv_bfloat16 g_Yh [MM * DD], g_Yl [MM * DD];
__device__ __nv_bfloat16 g_Hh [MM * FF], g_Hl [MM * FF];
// bf16 hi/lo weights
__device__ __nv_bfloat16 g_Wqh[DD * DD], g_Wql[DD * DD];
__device__ __nv_bfloat16 g_Wkh[DD * DD], g_Wkl[DD * DD];
__device__ __nv_bfloat16 g_Wvh[DD * DD], g_Wvl[DD * DD];
__device__ __nv_bfloat16 g_W1h[FF * DD], g_W1l[FF * DD];
__device__ __nv_bfloat16 g_W2h[DD * FF], g_W2l[DD * FF];

// ---------------------------------------------------------------------------
// Helpers
// ---------------------------------------------------------------------------
__device__ __forceinline__ uint32_t smem_u32(const void* p) {
    uint32_t a;
    asm("{ .reg .u64 t; cvta.to.shared.u64 t, %1; cvt.u32.u64 %0, t; }"
        : "=r"(a) : "l"(p));
    return a;
}

// hi/lo bf16 split of a float pair (low element = first arg)
__device__ __forceinline__ void bf16split2(float x, float y,
                                           __nv_bfloat162& hi, __nv_bfloat162& lo) {
    hi = __floats2bfloat162_rn(x, y);
    lo = __floats2bfloat162_rn(x - __bfloat162float(hi.x),
                               y - __bfloat162float(hi.y));
}

#define LDSM4(r0, r1, r2, r3, addr) \
    asm volatile("ldmatrix.sync.aligned.m8n8.x4.shared.b16 {%0,%1,%2,%3}, [%4];" \
                 : "=r"(r0), "=r"(r1), "=r"(r2), "=r"(r3) : "r"(addr))

#define MMA16816(d, a0, a1, a2, a3, b0, b1) \
    asm volatile("mma.sync.aligned.m16n8k16.row.col.f32.bf16.bf16.f32 " \
                 "{%0,%1,%2,%3}, {%4,%5,%6,%7}, {%8,%9}, {%0,%1,%2,%3};" \
                 : "+f"((d)[0]), "+f"((d)[1]), "+f"((d)[2]), "+f"((d)[3]) \
                 : "r"(a0), "r"(a1), "r"(a2), "r"(a3), "r"(b0), "r"(b1))

// ---------------------------------------------------------------------------
// Weight split: f32 -> bf16 hi + bf16 lo (residual). n multiple of 4.
// ---------------------------------------------------------------------------
__global__ __launch_bounds__(256)
void wsplit_kernel(const float* __restrict__ w,
                   __nv_bfloat16* __restrict__ hi,
                   __nv_bfloat16* __restrict__ lo, int n)
{
    int i = (blockIdx.x * blockDim.x + threadIdx.x) * 4;
    if (i >= n) return;
    float4 v = *(const float4*)(w + i);
    __nv_bfloat162 h0, l0, h1, l1;
    bf16split2(v.x, v.y, h0, l0);
    bf16split2(v.z, v.w, h1, l1);
    *(__nv_bfloat162*)(hi + i)     = h0;
    *(__nv_bfloat162*)(hi + i + 2) = h1;
    *(__nv_bfloat162*)(lo + i)     = l0;
    *(__nv_bfloat162*)(lo + i + 2) = l1;
}

// ---------------------------------------------------------------------------
// Block-wide sum reduction (256 threads, 8 warps)
// ---------------------------------------------------------------------------
__device__ __forceinline__ float block_reduce_sum(float v, float* sbuf) {
    int lane = threadIdx.x & 31;
    int warp = threadIdx.x >> 5;
    #pragma unroll
    for (int o = 16; o > 0; o >>= 1) v += __shfl_down_sync(0xffffffffu, v, o);
    if (lane == 0) sbuf[warp] = v;
    __syncthreads();
    if (warp == 0) {
        float t = (lane < 8) ? sbuf[lane] : 0.0f;
        #pragma unroll
        for (int o = 4; o > 0; o >>= 1) t += __shfl_down_sync(0xffffffffu, t, o);
        if (lane == 0) sbuf[0] = t;
    }
    __syncthreads();
    float r = sbuf[0];
    __syncthreads();
    return r;
}

// ---------------------------------------------------------------------------
// LayerNorm -> bf16 hi/lo output (+ optional pre-norm f32 store + threshold)
// ---------------------------------------------------------------------------
__global__ __launch_bounds__(256)
void ln_kernel(const float* __restrict__ x,
               const float* __restrict__ add,      // may be null
               const float* __restrict__ alpha,
               const float* __restrict__ bias,
               float* __restrict__ xr,             // may be null
               __nv_bfloat16* __restrict__ outHi,
               __nv_bfloat16* __restrict__ outLo,
               int applyThresh)
{
    __shared__ float sbuf[8];
    const int row = blockIdx.x;
    const int c4  = threadIdx.x * 4;
    const size_t base = (size_t)row * DD;

    float4 v = *(const float4*)(x + base + c4);
    if (add) {
        float4 a = *(const float4*)(add + base + c4);
        v.x += a.x; v.y += a.y; v.z += a.z; v.w += a.w;
    }
    if (xr) *(float4*)(xr + base + c4) = v;

    float s = v.x + v.y + v.z + v.w;
    s = block_reduce_sum(s, sbuf);
    const float mu = s * (1.0f / (float)DD);

    float dx0 = v.x - mu, dx1 = v.y - mu, dx2 = v.z - mu, dx3 = v.w - mu;
    float s2 = dx0*dx0 + dx1*dx1 + dx2*dx2 + dx3*dx3;
    s2 = block_reduce_sum(s2, sbuf);

    const float sd   = sqrtf(s2 * (1.0f / (float)(DD - 1)));
    const float rinv = 1.0f / (sd + EPS);

    float4 al = *(const float4*)(alpha + c4);
    float4 bi = *(const float4*)(bias  + c4);

    float o0 = al.x * dx0 * rinv + bi.x;
    float o1 = al.y * dx1 * rinv + bi.y;
    float o2 = al.z * dx2 * rinv + bi.z;
    float o3 = al.w * dx3 * rinv + bi.w;
    if (applyThresh) {
        if (o0 < THRESH) o0 = 0.0f;
        if (o1 < THRESH) o1 = 0.0f;
        if (o2 < THRESH) o2 = 0.0f;
        if (o3 < THRESH) o3 = 0.0f;
    }
    __nv_bfloat162 h0, l0, h1, l1;
    bf16split2(o0, o1, h0, l0);
    bf16split2(o2, o3, h1, l1);
    *(__nv_bfloat162*)(outHi + base + c4)     = h0;
    *(__nv_bfloat162*)(outHi + base + c4 + 2) = h1;
    *(__nv_bfloat162*)(outLo + base + c4)     = l0;
    *(__nv_bfloat162*)(outLo + base + c4 + 2) = l1;
}

// ---------------------------------------------------------------------------
// Tensor-core GEMM (mma.sync bf16x3): C[M,N] = A[M,K] @ W[N,K]^T + bias
// A, W given as bf16 (hi, lo) pairs. Accumulate ah*bh + ah*bl + al*bh in fp32.
// Output: f32 (+relu/+res) OR bf16 hi/lo split (+relu).
// CTA: 128x128 tile, 256 thr (8 warps, 2x4), warp tile 64x32, BK=32.
// Smem: 2 stages x 4 tiles (Ah, Al, Bh, Bl), each 128 rows x 32 bf16, stride 40.
// ---------------------------------------------------------------------------
#define GT_STRIDE 40                                // bf16 elems per smem row
#define GT_TILE_B (128 * GT_STRIDE * 2)             // 10240 bytes
#define GT_STAGE  (4 * GT_TILE_B)                   // 40960 bytes
#define GT_SMEM   (2 * GT_STAGE)                    // 81920 bytes

__global__ __launch_bounds__(256)
void mma_gemm_kernel(const __nv_bfloat16* __restrict__ Ah,
                     const __nv_bfloat16* __restrict__ Al,
                     const __nv_bfloat16* __restrict__ Bh,
                     const __nv_bfloat16* __restrict__ Bl,
                     const float* __restrict__ bias,
                     const float* __restrict__ res,   // may be null (f32 out only)
                     float* __restrict__ Cf,          // f32 out (or null)
                     __nv_bfloat16* __restrict__ Chi, // split out (or null)
                     __nv_bfloat16* __restrict__ Clo,
                     int N, int K, int doRelu)
{
    extern __shared__ char smc[];
    const int tid  = threadIdx.x;
    const int lane = tid & 31;
    const int wid  = tid >> 5;
    const int wm   = wid >> 2;          // 0..1
    const int wn   = wid & 3;           // 0..3
    const int m0 = blockIdx.y * 128;
    const int n0 = blockIdx.x * 128;
    const uint32_t sbase = smem_u32(smc);

    const __nv_bfloat16* gbase0 = Ah + (size_t)m0 * K;
    const __nv_bfloat16* gbase1 = Al + (size_t)m0 * K;
    const __nv_bfloat16* gbase2 = Bh + (size_t)n0 * K;
    const __nv_bfloat16* gbase3 = Bl + (size_t)n0 * K;

    float acc[4][4][4];
    #pragma unroll
    for (int a = 0; a < 4; ++a)
        #pragma unroll
        for (int b = 0; b < 4; ++b)
            #pragma unroll
            for (int c = 0; c < 4; ++c) acc[a][b][c] = 0.0f;

    // loader: i=0..7 -> tile = i>>1, rem = (i&1)*256 + tid, row = rem>>2, seg = rem&3
    const int lrow0 = tid >> 2,         lseg0 = tid & 3;          // i even
    const int lrow1 = (256 + tid) >> 2, lseg1 = (256 + tid) & 3;  // i odd

    // ldmatrix address params
    const int arow  = lane & 15;
    const int acol8 = (lane >> 4) << 3;
    const int brow  = lane & 7;
    const int bgrp  = lane >> 3;
    const int bnoff = (bgrp >> 1) << 3;   // 0 or 8
    const int bkoff = (bgrp & 1) << 3;    // 0 or 8

    const int nt = K >> 5;                // K/32 chunks

    // preload chunk 0 -> stage 0
    {
        #pragma unroll
        for (int i = 0; i < 8; ++i) {
            const int row = (i & 1) ? lrow1 : lrow0;
            const int seg = (i & 1) ? lseg1 : lseg0;
            const __nv_bfloat16* gb = (i >> 1) == 0 ? gbase0 :
                                      (i >> 1) == 1 ? gbase1 :
                                      (i >> 1) == 2 ? gbase2 : gbase3;
            uint4 v = *(const uint4*)(gb + (size_t)row * K + seg * 8);
            *(uint4*)(smc + (i >> 1) * GT_TILE_B + (row * GT_STRIDE + seg * 8) * 2) = v;
        }
    }
    __syncthreads();

    for (int t = 0; t < nt; ++t) {
        const int buf = t & 1;
        const bool has = (t + 1 < nt);
        uint4 pre[8];
        if (has) {
            const int kc = (t + 1) << 5;
            #pragma unroll
            for (int i = 0; i < 8; ++i) {
                const int row = (i & 1) ? lrow1 : lrow0;
                const int seg = (i & 1) ? lseg1 : lseg0;
                const __nv_bfloat16* gb = (i >> 1) == 0 ? gbase0 :
                                          (i >> 1) == 1 ? gbase1 :
                                          (i >> 1) == 2 ? gbase2 : gbase3;
                pre[i] = *(const uint4*)(gb + (size_t)row * K + kc + seg * 8);
            }
        }

        const uint32_t sAh = sbase + buf * GT_STAGE;
        const uint32_t sAl = sAh + GT_TILE_B;
        const uint32_t sBh = sAh + 2 * GT_TILE_B;
        const uint32_t sBl = sAh + 3 * GT_TILE_B;

        #pragma unroll
        for (int ks = 0; ks < 2; ++ks) {
            const int kc16 = ks << 4;
            uint32_t ah[4][4], al[4][4], bh[2][4], bl[2][4];
            #pragma unroll
            for (int mf = 0; mf < 4; ++mf) {
                const uint32_t off =
                    ((wm * 64 + mf * 16 + arow) * GT_STRIDE + kc16 + acol8) * 2;
                LDSM4(ah[mf][0], ah[mf][1], ah[mf][2], ah[mf][3], sAh + off);
                LDSM4(al[mf][0], al[mf][1], al[mf][2], al[mf][3], sAl + off);
            }
            #pragma unroll
            for (int p = 0; p < 2; ++p) {
                const uint32_t off =
                    ((wn * 32 + p * 16 + bnoff + brow) * GT_STRIDE + kc16 + bkoff) * 2;
                LDSM4(bh[p][0], bh[p][1], bh[p][2], bh[p][3], sBh + off);
                LDSM4(bl[p][0], bl[p][1], bl[p][2], bl[p][3], sBl + off);
            }
            #pragma unroll
            for (int mf = 0; mf < 4; ++mf)
                #pragma unroll
                for (int nf = 0; nf < 4; ++nf) {
                    const int p = nf >> 1, q = (nf & 1) << 1;
                    MMA16816(acc[mf][nf], ah[mf][0], ah[mf][1], ah[mf][2], ah[mf][3],
                             bh[p][q], bh[p][q + 1]);
                    MMA16816(acc[mf][nf], ah[mf][0], ah[mf][1], ah[mf][2], ah[mf][3],
                             bl[p][q], bl[p][q + 1]);
                    MMA16816(acc[mf][nf], al[mf][0], al[mf][1], al[mf][2], al[mf][3],
                             bh[p][q], bh[p][q + 1]);
                }
        }

        if (has) {
            char* s = smc + (buf ^ 1) * GT_STAGE;
            #pragma unroll
            for (int i = 0; i < 8; ++i) {
                const int row = (i & 1) ? lrow1 : lrow0;
                const int seg = (i & 1) ? lseg1 : lseg0;
                *(uint4*)(s + (i >> 1) * GT_TILE_B + (row * GT_STRIDE + seg * 8) * 2) = pre[i];
            }
            __syncthreads();
        }
    }

    // ---- epilogue ----
    #pragma unroll
    for (int mf = 0; mf < 4; ++mf) {
        #pragma unroll
        for (int nf = 0; nf < 4; ++nf) {
            const int col = n0 + wn * 32 + nf * 8 + ((lane & 3) << 1);
            const float b0 = bias[col], b1 = bias[col + 1];
            #pragma unroll
            for (int h = 0; h < 2; ++h) {
                const int row = m0 + wm * 64 + mf * 16 + (lane >> 2) + h * 8;
                float o0 = acc[mf][nf][h * 2]     + b0;
                float o1 = acc[mf][nf][h * 2 + 1] + b1;
                if (doRelu) { o0 = fmaxf(o0, 0.0f); o1 = fmaxf(o1, 0.0f); }
                const size_t off = (size_t)row * N + col;
                if (Cf) {
                    if (res) {
                        float2 r2 = *(const float2*)(res + off);
                        o0 += r2.x; o1 += r2.y;
                    }
                    *(float2*)(Cf + off) = make_float2(o0, o1);
                } else {
                    __nv_bfloat162 hh, ll;
                    bf16split2(o0, o1, hh, ll);
                    *(__nv_bfloat162*)(Chi + off) = hh;
                    *(__nv_bfloat162*)(Clo + off) = ll;
                }
            }
        }
    }
}

// ---------------------------------------------------------------------------
// Flash attention, fp32 (unchanged from R3 passing version)
// ---------------------------------------------------------------------------
#define ATTN_SMEM_BYTES ((64*64 + 64*68 + 64*64 + 64*64) * 4)

__global__ __launch_bounds__(128)
void attn_kernel(const float* __restrict__ Qg,
                 const float* __restrict__ Kg,
                 const float* __restrict__ Vg,
                 float* __restrict__ Og)
{
    extern __shared__ float sm[];
    float (*Qs)[64] = (float(*)[64])(sm);
    float (*Ks)[68] = (float(*)[68])(sm + 64*64);
    float (*Vs)[64] = (float(*)[64])(sm + 64*64 + 64*68);
    float (*Ps)[64] = (float(*)[64])(sm + 64*64 + 64*68 + 64*64);

    const int qt = blockIdx.x;
    const int h  = blockIdx.y;
    const int b  = blockIdx.z;
    const int tid = threadIdx.x;
    const int tq = tid >> 3;
    const int tk = tid & 7;
    const float scale = 0.125f;

    {
        const float* qbase = Qg + ((size_t)(b * SS + qt * 64)) * DD + h * DH;
        for (int f = tid; f < 1024; f += 128) {
            const int r = f >> 4, c = (f & 15) << 2;
            *(float4*)&Qs[r][c] = *(const float4*)(qbase + (size_t)r * DD + c);
        }
    }

    float m[4], l[4], acc[4][8];
    #pragma unroll
    for (int i = 0; i < 4; ++i) {
        m[i] = -1e30f; l[i] = 0.0f;
        #pragma unroll
        for (int j = 0; j < 8; ++j) acc[i][j] = 0.0f;
    }

    for (int kt = 0; kt < SS / 64; ++kt) {
        __syncthreads();
        {
            const float* kbase = Kg + ((size_t)(b * SS + kt * 64)) * DD + h * DH;
            const float* vbase = Vg + ((size_t)(b * SS + kt * 64)) * DD + h * DH;
            for (int f = tid; f < 1024; f += 128) {
                const int r = f >> 4, c = (f & 15) << 2;
                *(float4*)&Ks[r][c] = *(const float4*)(kbase + (size_t)r * DD + c);
                *(float4*)&Vs[r][c] = *(const float4*)(vbase + (size_t)r * DD + c);
            }
        }
        __syncthreads();

        float s[4][8];
        #pragma unroll
        for (int i = 0; i < 4; ++i)
            #pragma unroll
            for (int j = 0; j < 8; ++j) s[i][j] = 0.0f;

        #pragma unroll 2
        for (int d = 0; d < DH; d += 4) {
            float4 qa[4], kb[8];
            #pragma unroll
            for (int i = 0; i < 4; ++i) qa[i] = *(const float4*)&Qs[tq * 4 + i][d];
            #pragma unroll
            for (int j = 0; j < 8; ++j) kb[j] = *(const float4*)&Ks[tk + 8 * j][d];
            #pragma unroll
            for (int i = 0; i < 4; ++i)
                #pragma unroll
                for (int j = 0; j < 8; ++j) {
                    s[i][j] = fmaf(qa[i].x, kb[j].x, s[i][j]);
                    s[i][j] = fmaf(qa[i].y, kb[j].y, s[i][j]);
                    s[i][j] = fmaf(qa[i].z, kb[j].z, s[i][j]);
                    s[i][j] = fmaf(qa[i].w, kb[j].w, s[i][j]);
                }
        }

        #pragma unroll
        for (int i = 0; i < 4; ++i) {
            float rm = -1e30f;
            #pragma unroll
            for (int j = 0; j < 8; ++j) { s[i][j] *= scale; rm = fmaxf(rm, s[i][j]); }
            #pragma unroll
            for (int o = 1; o < 8; o <<= 1)
                rm = fmaxf(rm, __shfl_xor_sync(0xffffffffu, rm, o));
            const float mn   = fmaxf(m[i], rm);
            const float corr = __expf(m[i] - mn);
            float rs = 0.0f;
            #pragma unroll
            for (int j = 0; j < 8; ++j) {
                const float p = __expf(s[i][j] - mn);
                Ps[tq * 4 + i][tk + 8 * j] = p;
                rs += p;
            }
            #pragma unroll
            for (int o = 1; o < 8; o <<= 1)
                rs += __shfl_xor_sync(0xffffffffu, rs, o);
            l[i] = l[i] * corr + rs;
            m[i] = mn;
            #pragma unroll
            for (int j = 0; j < 8; ++j) acc[i][j] *= corr;
        }
        __syncwarp();

        #pragma unroll 4
        for (int k = 0; k < 64; ++k) {
            float4 v0 = *(const float4*)&Vs[k][tk * 8];
            float4 v1 = *(const float4*)&Vs[k][tk * 8 + 4];
            float pv[4];
            #pragma unroll
            for (int i = 0; i < 4; ++i) pv[i] = Ps[tq * 4 + i][k];
            #pragma unroll
            for (int i = 0; i < 4; ++i) {
                acc[i][0] = fmaf(pv[i], v0.x, acc[i][0]);
                acc[i][1] = fmaf(pv[i], v0.y, acc[i][1]);
                acc[i][2] = fmaf(pv[i], v0.z, acc[i][2]);
                acc[i][3] = fmaf(pv[i], v0.w, acc[i][3]);
                acc[i][4] = fmaf(pv[i], v1.x, acc[i][4]);
                acc[i][5] = fmaf(pv[i], v1.y, acc[i][5]);
                acc[i][6] = fmaf(pv[i], v1.z, acc[i][6]);
                acc[i][7] = fmaf(pv[i], v1.w, acc[i][7]);
            }
        }
    }

    #pragma unroll
    for (int i = 0; i < 4; ++i) {
        const float inv = 1.0f / l[i];
        const size_t row = (size_t)(b * SS + qt * 64 + tq * 4 + i);
        float* ob = Og + row * DD + h * DH + tk * 8;
        *(float4*)(ob)     = make_float4(acc[i][0]*inv, acc[i][1]*inv, acc[i][2]*inv, acc[i][3]*inv);
        *(float4*)(ob + 4) = make_float4(acc[i][4]*inv, acc[i][5]*inv, acc[i][6]*inv, acc[i][7]*inv);
    }
}

// ---------------------------------------------------------------------------
// Launch
// ---------------------------------------------------------------------------
extern "C" void kernel_launch(void* const* d_in, const int* in_sizes, int n_in,
                              void* d_out, int out_size)
{
    const float* x      = (const float*)d_in[0];
    const float* alpha1 = (const float*)d_in[1];
    const float* bias1  = (const float*)d_in[2];
    const float* alpha2 = (const float*)d_in[3];
    const float* bias2  = (const float*)d_in[4];
    const float* wq     = (const float*)d_in[5];
    const float* bq     = (const float*)d_in[6];
    const float* wk     = (const float*)d_in[7];
    const float* bk     = (const float*)d_in[8];
    const float* wv     = (const float*)d_in[9];
    const float* bv     = (const float*)d_in[10];
    const float* w1     = (const float*)d_in[11];
    const float* b1     = (const float*)d_in[12];
    const float* w2     = (const float*)d_in[13];
    const float* b2     = (const float*)d_in[14];
    float* out = (float*)d_out;

    float *Qb, *Kb, *Vb, *AT, *XR;
    cudaGetSymbolAddress((void**)&Qb, g_Q);
    cudaGetSymbolAddress((void**)&Kb, g_K);
    cudaGetSymbolAddress((void**)&Vb, g_V);
    cudaGetSymbolAddress((void**)&AT, g_AT);
    cudaGetSymbolAddress((void**)&XR, g_XR);
    __nv_bfloat16 *X2h, *X2l, *Yh, *Yl, *Hh, *Hl;
    cudaGetSymbolAddress((void**)&X2h, g_X2h);
    cudaGetSymbolAddress((void**)&X2l, g_X2l);
    cudaGetSymbolAddress((void**)&Yh,  g_Yh);
    cudaGetSymbolAddress((void**)&Yl,  g_Yl);
    cudaGetSymbolAddress((void**)&Hh,  g_Hh);
    cudaGetSymbolAddress((void**)&Hl,  g_Hl);
    __nv_bfloat16 *Wqh, *Wql, *Wkh, *Wkl, *Wvh, *Wvl, *W1h, *W1l, *W2h, *W2l;
    cudaGetSymbolAddress((void**)&Wqh, g_Wqh);
    cudaGetSymbolAddress((void**)&Wql, g_Wql);
    cudaGetSymbolAddress((void**)&Wkh, g_Wkh);
    cudaGetSymbolAddress((void**)&Wkl, g_Wkl);
    cudaGetSymbolAddress((void**)&Wvh, g_Wvh);
    cudaGetSymbolAddress((void**)&Wvl, g_Wvl);
    cudaGetSymbolAddress((void**)&W1h, g_W1h);
    cudaGetSymbolAddress((void**)&W1l, g_W1l);
    cudaGetSymbolAddress((void**)&W2h, g_W2h);
    cudaGetSymbolAddress((void**)&W2l, g_W2l);

    cudaFuncSetAttribute(attn_kernel,
                         cudaFuncAttributeMaxDynamicSharedMemorySize,
                         ATTN_SMEM_BYTES);
    cudaFuncSetAttribute(mma_gemm_kernel,
                         cudaFuncAttributeMaxDynamicSharedMemorySize,
                         GT_SMEM);

    // 0. weight splits (f32 -> bf16 hi/lo)
    wsplit_kernel<<<(DD * DD / 4 + 255) / 256, 256>>>(wq, Wqh, Wql, DD * DD);
    wsplit_kernel<<<(DD * DD / 4 + 255) / 256, 256>>>(wk, Wkh, Wkl, DD * DD);
    wsplit_kernel<<<(DD * DD / 4 + 255) / 256, 256>>>(wv, Wvh, Wvl, DD * DD);
    wsplit_kernel<<<(FF * DD / 4 + 255) / 256, 256>>>(w1, W1h, W1l, FF * DD);
    wsplit_kernel<<<(DD * FF / 4 + 255) / 256, 256>>>(w2, W2h, W2l, DD * FF);

    // 1. pre-norm 1 -> split bf16
    ln_kernel<<<MM, 256>>>(x, nullptr, alpha1, bias1, nullptr, X2h, X2l, 0);

    // 2-4. Q, K, V projections (tensor cores)
    dim3 gqkv(DD / 128, MM / 128);
    mma_gemm_kernel<<<gqkv, 256, GT_SMEM>>>(X2h, X2l, Wqh, Wql, bq, nullptr,
                                            Qb, nullptr, nullptr, DD, DD, 0);
    mma_gemm_kernel<<<gqkv, 256, GT_SMEM>>>(X2h, X2l, Wkh, Wkl, bk, nullptr,
                                            Kb, nullptr, nullptr, DD, DD, 0);
    mma_gemm_kernel<<<gqkv, 256, GT_SMEM>>>(X2h, X2l, Wvh, Wvl, bv, nullptr,
                                            Vb, nullptr, nullptr, DD, DD, 0);

    // 5. attention
    attn_kernel<<<dim3(SS / 64, HH, BB), 128, ATTN_SMEM_BYTES>>>(Qb, Kb, Vb, AT);

    // 6. residual + norm 2 + threshold -> XR (f32) + split Y
    ln_kernel<<<MM, 256>>>(x, AT, alpha2, bias2, XR, Yh, Yl, 1);

    // 7. FFN1 (relu, split bf16 out)
    mma_gemm_kernel<<<dim3(FF / 128, MM / 128), 256, GT_SMEM>>>(
        Yh, Yl, W1h, W1l, b1, nullptr, nullptr, Hh, Hl, FF, DD, 1);

    // 8. FFN2 (+bias +residual, f32 out)
    mma_gemm_kernel<<<dim3(DD / 128, MM / 128), 256, GT_SMEM>>>(
        Hh, Hl, W2h, W2l, b2, XR, out, nullptr, nullptr, DD, FF, 0);
}

// round 10
// speedup vs baseline: 2.9943x; 1.7404x over previous
#include <cuda_runtime.h>
#include <cuda_bf16.h>
#include <math.h>
#include <stdint.h>

// ---------------------------------------------------------------------------
// Problem constants
// ---------------------------------------------------------------------------
#define BB   4
#define SS   2048
#define DD   1024
#define FF   4096
#define HH   16
#define DH   64
#define MM   (BB * SS)          // 8192 rows
#define EPS  1e-6f
#define THRESH 0.15f

// ---------------------------------------------------------------------------
// Scratch buffers (device globals; no allocations allowed)
// ---------------------------------------------------------------------------
// fp32
__device__ float g_AT[MM * DD];
__device__ float g_XR[MM * DD];
// bf16 hi/lo activations
__device__ __nv_bfloat16 g_X2h[MM * DD], g_X2l[MM * DD];
__device__ __nv_bfloat16 g_Yh [MM * DD], g_Yl [MM * DD];
__device__ __nv_bfloat16 g_Hh [MM * FF], g_Hl [MM * FF];
// bf16 hi/lo Q, K, V (written by the QKV GEMMs' split epilogue)
__device__ __nv_bfloat16 g_Qh[MM * DD], g_Ql[MM * DD];
__device__ __nv_bfloat16 g_Kh[MM * DD], g_Kl[MM * DD];
__device__ __nv_bfloat16 g_Vh[MM * DD], g_Vl[MM * DD];
// bf16 hi/lo weights
__device__ __nv_bfloat16 g_Wqh[DD * DD], g_Wql[DD * DD];
__device__ __nv_bfloat16 g_Wkh[DD * DD], g_Wkl[DD * DD];
__device__ __nv_bfloat16 g_Wvh[DD * DD], g_Wvl[DD * DD];
__device__ __nv_bfloat16 g_W1h[FF * DD], g_W1l[FF * DD];
__device__ __nv_bfloat16 g_W2h[DD * FF], g_W2l[DD * FF];

// ---------------------------------------------------------------------------
// Helpers
// ---------------------------------------------------------------------------
__device__ __forceinline__ uint32_t smem_u32(const void* p) {
    uint32_t a;
    asm("{ .reg .u64 t; cvta.to.shared.u64 t, %1; cvt.u32.u64 %0, t; }"
        : "=r"(a) : "l"(p));
    return a;
}

// hi/lo bf16 split of a float pair (low element = first arg)
__device__ __forceinline__ void bf16split2(float x, float y,
                                           __nv_bfloat162& hi, __nv_bfloat162& lo) {
    hi = __floats2bfloat162_rn(x, y);
    lo = __floats2bfloat162_rn(x - __bfloat162float(hi.x),
                               y - __bfloat162float(hi.y));
}

__device__ __forceinline__ uint32_t pack_bf16x2(float lo, float hi) {
    __nv_bfloat162 t = __floats2bfloat162_rn(lo, hi);
    return *(uint32_t*)&t;
}

#define LDSM4(r0, r1, r2, r3, addr) \
    asm volatile("ldmatrix.sync.aligned.m8n8.x4.shared.b16 {%0,%1,%2,%3}, [%4];" \
                 : "=r"(r0), "=r"(r1), "=r"(r2), "=r"(r3) : "r"(addr))

#define LDSM4T(r0, r1, r2, r3, addr) \
    asm volatile("ldmatrix.sync.aligned.m8n8.x4.trans.shared.b16 {%0,%1,%2,%3}, [%4];" \
                 : "=r"(r0), "=r"(r1), "=r"(r2), "=r"(r3) : "r"(addr))

#define MMA16816(d, a0, a1, a2, a3, b0, b1) \
    asm volatile("mma.sync.aligned.m16n8k16.row.col.f32.bf16.bf16.f32 " \
                 "{%0,%1,%2,%3}, {%4,%5,%6,%7}, {%8,%9}, {%0,%1,%2,%3};" \
                 : "+f"((d)[0]), "+f"((d)[1]), "+f"((d)[2]), "+f"((d)[3]) \
                 : "r"(a0), "r"(a1), "r"(a2), "r"(a3), "r"(b0), "r"(b1))

// ---------------------------------------------------------------------------
// Weight split: f32 -> bf16 hi + bf16 lo (residual). n multiple of 4.
// ---------------------------------------------------------------------------
__global__ __launch_bounds__(256)
void wsplit_kernel(const float* __restrict__ w,
                   __nv_bfloat16* __restrict__ hi,
                   __nv_bfloat16* __restrict__ lo, int n)
{
    int i = (blockIdx.x * blockDim.x + threadIdx.x) * 4;
    if (i >= n) return;
    float4 v = *(const float4*)(w + i);
    __nv_bfloat162 h0, l0, h1, l1;
    bf16split2(v.x, v.y, h0, l0);
    bf16split2(v.z, v.w, h1, l1);
    *(__nv_bfloat162*)(hi + i)     = h0;
    *(__nv_bfloat162*)(hi + i + 2) = h1;
    *(__nv_bfloat162*)(lo + i)     = l0;
    *(__nv_bfloat162*)(lo + i + 2) = l1;
}

// ---------------------------------------------------------------------------
// Block-wide sum reduction (256 threads, 8 warps)
// ---------------------------------------------------------------------------
__device__ __forceinline__ float block_reduce_sum(float v, float* sbuf) {
    int lane = threadIdx.x & 31;
    int warp = threadIdx.x >> 5;
    #pragma unroll
    for (int o = 16; o > 0; o >>= 1) v += __shfl_down_sync(0xffffffffu, v, o);
    if (lane == 0) sbuf[warp] = v;
    __syncthreads();
    if (warp == 0) {
        float t = (lane < 8) ? sbuf[lane] : 0.0f;
        #pragma unroll
        for (int o = 4; o > 0; o >>= 1) t += __shfl_down_sync(0xffffffffu, t, o);
        if (lane == 0) sbuf[0] = t;
    }
    __syncthreads();
    float r = sbuf[0];
    __syncthreads();
    return r;
}

// ---------------------------------------------------------------------------
// LayerNorm -> bf16 hi/lo output (+ optional pre-norm f32 store + threshold)
// ---------------------------------------------------------------------------
__global__ __launch_bounds__(256)
void ln_kernel(const float* __restrict__ x,
               const float* __restrict__ add,      // may be null
               const float* __restrict__ alpha,
               const float* __restrict__ bias,
               float* __restrict__ xr,             // may be null
               __nv_bfloat16* __restrict__ outHi,
               __nv_bfloat16* __restrict__ outLo,
               int applyThresh)
{
    __shared__ float sbuf[8];
    const int row = blockIdx.x;
    const int c4  = threadIdx.x * 4;
    const size_t base = (size_t)row * DD;

    float4 v = *(const float4*)(x + base + c4);
    if (add) {
        float4 a = *(const float4*)(add + base + c4);
        v.x += a.x; v.y += a.y; v.z += a.z; v.w += a.w;
    }
    if (xr) *(float4*)(xr + base + c4) = v;

    float s = v.x + v.y + v.z + v.w;
    s = block_reduce_sum(s, sbuf);
    const float mu = s * (1.0f / (float)DD);

    float dx0 = v.x - mu, dx1 = v.y - mu, dx2 = v.z - mu, dx3 = v.w - mu;
    float s2 = dx0*dx0 + dx1*dx1 + dx2*dx2 + dx3*dx3;
    s2 = block_reduce_sum(s2, sbuf);

    const float sd   = sqrtf(s2 * (1.0f / (float)(DD - 1)));
    const float rinv = 1.0f / (sd + EPS);

    float4 al = *(const float4*)(alpha + c4);
    float4 bi = *(const float4*)(bias  + c4);

    float o0 = al.x * dx0 * rinv + bi.x;
    float o1 = al.y * dx1 * rinv + bi.y;
    float o2 = al.z * dx2 * rinv + bi.z;
    float o3 = al.w * dx3 * rinv + bi.w;
    if (applyThresh) {
        if (o0 < THRESH) o0 = 0.0f;
        if (o1 < THRESH) o1 = 0.0f;
        if (o2 < THRESH) o2 = 0.0f;
        if (o3 < THRESH) o3 = 0.0f;
    }
    __nv_bfloat162 h0, l0, h1, l1;
    bf16split2(o0, o1, h0, l0);
    bf16split2(o2, o3, h1, l1);
    *(__nv_bfloat162*)(outHi + base + c4)     = h0;
    *(__nv_bfloat162*)(outHi + base + c4 + 2) = h1;
    *(__nv_bfloat162*)(outLo + base + c4)     = l0;
    *(__nv_bfloat162*)(outLo + base + c4 + 2) = l1;
}

// ---------------------------------------------------------------------------
// Tensor-core GEMM (mma.sync bf16x3): C[M,N] = A[M,K] @ W[N,K]^T + bias
// (unchanged from the R9 passing version)
// ---------------------------------------------------------------------------
#define GT_STRIDE 40                                // bf16 elems per smem row
#define GT_TILE_B (128 * GT_STRIDE * 2)             // 10240 bytes
#define GT_STAGE  (4 * GT_TILE_B)                   // 40960 bytes
#define GT_SMEM   (2 * GT_STAGE)                    // 81920 bytes

__global__ __launch_bounds__(256)
void mma_gemm_kernel(const __nv_bfloat16* __restrict__ Ah,
                     const __nv_bfloat16* __restrict__ Al,
                     const __nv_bfloat16* __restrict__ Bh,
                     const __nv_bfloat16* __restrict__ Bl,
                     const float* __restrict__ bias,
                     const float* __restrict__ res,   // may be null (f32 out only)
                     float* __restrict__ Cf,          // f32 out (or null)
                     __nv_bfloat16* __restrict__ Chi, // split out (or null)
                     __nv_bfloat16* __restrict__ Clo,
                     int N, int K, int doRelu)
{
    extern __shared__ char smc[];
    const int tid  = threadIdx.x;
    const int lane = tid & 31;
    const int wid  = tid >> 5;
    const int wm   = wid >> 2;          // 0..1
    const int wn   = wid & 3;           // 0..3
    const int m0 = blockIdx.y * 128;
    const int n0 = blockIdx.x * 128;
    const uint32_t sbase = smem_u32(smc);

    const __nv_bfloat16* gbase0 = Ah + (size_t)m0 * K;
    const __nv_bfloat16* gbase1 = Al + (size_t)m0 * K;
    const __nv_bfloat16* gbase2 = Bh + (size_t)n0 * K;
    const __nv_bfloat16* gbase3 = Bl + (size_t)n0 * K;

    float acc[4][4][4];
    #pragma unroll
    for (int a = 0; a < 4; ++a)
        #pragma unroll
        for (int b = 0; b < 4; ++b)
            #pragma unroll
            for (int c = 0; c < 4; ++c) acc[a][b][c] = 0.0f;

    const int lrow0 = tid >> 2,         lseg0 = tid & 3;
    const int lrow1 = (256 + tid) >> 2, lseg1 = (256 + tid) & 3;

    const int arow  = lane & 15;
    const int acol8 = (lane >> 4) << 3;
    const int brow  = lane & 7;
    const int bgrp  = lane >> 3;
    const int bnoff = (bgrp >> 1) << 3;
    const int bkoff = (bgrp & 1) << 3;

    const int nt = K >> 5;

    {
        #pragma unroll
        for (int i = 0; i < 8; ++i) {
            const int row = (i & 1) ? lrow1 : lrow0;
            const int seg = (i & 1) ? lseg1 : lseg0;
            const __nv_bfloat16* gb = (i >> 1) == 0 ? gbase0 :
                                      (i >> 1) == 1 ? gbase1 :
                                      (i >> 1) == 2 ? gbase2 : gbase3;
            uint4 v = *(const uint4*)(gb + (size_t)row * K + seg * 8);
            *(uint4*)(smc + (i >> 1) * GT_TILE_B + (row * GT_STRIDE + seg * 8) * 2) = v;
        }
    }
    __syncthreads();

    for (int t = 0; t < nt; ++t) {
        const int buf = t & 1;
        const bool has = (t + 1 < nt);
        uint4 pre[8];
        if (has) {
            const int kc = (t + 1) << 5;
            #pragma unroll
            for (int i = 0; i < 8; ++i) {
                const int row = (i & 1) ? lrow1 : lrow0;
                const int seg = (i & 1) ? lseg1 : lseg0;
                const __nv_bfloat16* gb = (i >> 1) == 0 ? gbase0 :
                                          (i >> 1) == 1 ? gbase1 :
                                          (i >> 1) == 2 ? gbase2 : gbase3;
                pre[i] = *(const uint4*)(gb + (size_t)row * K + kc + seg * 8);
            }
        }

        const uint32_t sAh = sbase + buf * GT_STAGE;
        const uint32_t sAl = sAh + GT_TILE_B;
        const uint32_t sBh = sAh + 2 * GT_TILE_B;
        const uint32_t sBl = sAh + 3 * GT_TILE_B;

        #pragma unroll
        for (int ks = 0; ks < 2; ++ks) {
            const int kc16 = ks << 4;
            uint32_t ah[4][4], al[4][4], bh[2][4], bl[2][4];
            #pragma unroll
            for (int mf = 0; mf < 4; ++mf) {
                const uint32_t off =
                    ((wm * 64 + mf * 16 + arow) * GT_STRIDE + kc16 + acol8) * 2;
                LDSM4(ah[mf][0], ah[mf][1], ah[mf][2], ah[mf][3], sAh + off);
                LDSM4(al[mf][0], al[mf][1], al[mf][2], al[mf][3], sAl + off);
            }
            #pragma unroll
            for (int p = 0; p < 2; ++p) {
                const uint32_t off =
                    ((wn * 32 + p * 16 + bnoff + brow) * GT_STRIDE + kc16 + bkoff) * 2;
                LDSM4(bh[p][0], bh[p][1], bh[p][2], bh[p][3], sBh + off);
                LDSM4(bl[p][0], bl[p][1], bl[p][2], bl[p][3], sBl + off);
            }
            #pragma unroll
            for (int mf = 0; mf < 4; ++mf)
                #pragma unroll
                for (int nf = 0; nf < 4; ++nf) {
                    const int p = nf >> 1, q = (nf & 1) << 1;
                    MMA16816(acc[mf][nf], ah[mf][0], ah[mf][1], ah[mf][2], ah[mf][3],
                             bh[p][q], bh[p][q + 1]);
                    MMA16816(acc[mf][nf], ah[mf][0], ah[mf][1], ah[mf][2], ah[mf][3],
                             bl[p][q], bl[p][q + 1]);
                    MMA16816(acc[mf][nf], al[mf][0], al[mf][1], al[mf][2], al[mf][3],
                             bh[p][q], bh[p][q + 1]);
                }
        }

        if (has) {
            char* s = smc + (buf ^ 1) * GT_STAGE;
            #pragma unroll
            for (int i = 0; i < 8; ++i) {
                const int row = (i & 1) ? lrow1 : lrow0;
                const int seg = (i & 1) ? lseg1 : lseg0;
                *(uint4*)(s + (i >> 1) * GT_TILE_B + (row * GT_STRIDE + seg * 8) * 2) = pre[i];
            }
            __syncthreads();
        }
    }

    // ---- epilogue ----
    #pragma unroll
    for (int mf = 0; mf < 4; ++mf) {
        #pragma unroll
        for (int nf = 0; nf < 4; ++nf) {
            const int col = n0 + wn * 32 + nf * 8 + ((lane & 3) << 1);
            const float b0 = bias[col], b1 = bias[col + 1];
            #pragma unroll
            for (int h = 0; h < 2; ++h) {
                const int row = m0 + wm * 64 + mf * 16 + (lane >> 2) + h * 8;
                float o0 = acc[mf][nf][h * 2]     + b0;
                float o1 = acc[mf][nf][h * 2 + 1] + b1;
                if (doRelu) { o0 = fmaxf(o0, 0.0f); o1 = fmaxf(o1, 0.0f); }
                const size_t off = (size_t)row * N + col;
                if (Cf) {
                    if (res) {
                        float2 r2 = *(const float2*)(res + off);
                        o0 += r2.x; o1 += r2.y;
                    }
                    *(float2*)(Cf + off) = make_float2(o0, o1);
                } else {
                    __nv_bfloat162 hh, ll;
                    bf16split2(o0, o1, hh, ll);
                    *(__nv_bfloat162*)(Chi + off) = hh;
                    *(__nv_bfloat162*)(Clo + off) = ll;
                }
            }
        }
    }
}

// ---------------------------------------------------------------------------
// Tensor-core flash attention (mma.sync bf16).
// One block = (b, h, 64 q-rows). 128 threads, 4 warps; warp w owns q rows
// w*16..w*16+15. K/V tiles of 64 rows. Scores = bf16x3 (qh*kh+qh*kl+ql*kh),
// fp32 accum; softmax on C-fragments; P repacked to A-frags in registers;
// O += P(bf16) @ V(bf16 hi) with ldmatrix.trans for V.
// Smem: Qh | Ql | Kh | Kl | Vh tiles, 64 x 72 bf16 each (stride 72 = 144 B,
// conflict-free ldmatrix phases).
// ---------------------------------------------------------------------------
#define AT_STRIDE 72
#define AT_TILE_B (64 * AT_STRIDE * 2)    // 9216 bytes
#define AT_SMEM   (5 * AT_TILE_B)         // 46080 bytes

__global__ __launch_bounds__(128)
void mma_attn_kernel(const __nv_bfloat16* __restrict__ Qh,
                     const __nv_bfloat16* __restrict__ Ql,
                     const __nv_bfloat16* __restrict__ Kh,
                     const __nv_bfloat16* __restrict__ Kl,
                     const __nv_bfloat16* __restrict__ Vh,
                     float* __restrict__ Og)
{
    extern __shared__ char smc[];
    const uint32_t sb  = smem_u32(smc);
    const uint32_t sQh = sb;
    const uint32_t sQl = sb + AT_TILE_B;
    const uint32_t sKh = sb + 2 * AT_TILE_B;
    const uint32_t sKl = sb + 3 * AT_TILE_B;
    const uint32_t sVh = sb + 4 * AT_TILE_B;

    const int tid = threadIdx.x, lane = tid & 31, wid = tid >> 5;
    const int qt = blockIdx.x, h = blockIdx.y, b = blockIdx.z;
    const int wq0 = wid * 16;
    const float scale = 0.125f;   // 1/sqrt(64)

    const size_t qrow0 = (size_t)(b * SS + qt * 64);
    const __nv_bfloat16* gQh = Qh + qrow0 * DD + h * DH;
    const __nv_bfloat16* gQl = Ql + qrow0 * DD + h * DH;

    // load Q hi/lo tiles (64 x 64)
    for (int f = tid; f < 512; f += 128) {
        const int r = f >> 3, c8 = (f & 7) * 8;
        const size_t go = (size_t)r * DD + c8;
        const uint32_t so = (uint32_t)(r * AT_STRIDE + c8) * 2;
        *(uint4*)(smc + so)             = *(const uint4*)(gQh + go);
        *(uint4*)(smc + AT_TILE_B + so) = *(const uint4*)(gQl + go);
    }
    __syncthreads();

    // Q A-fragments, held for the whole loop
    const int arow = lane & 15, acol8 = (lane >> 4) << 3;
    const int brow = lane & 7, bgrp = lane >> 3;
    const int bn8 = (bgrp >> 1) << 3, bk8 = (bgrp & 1) << 3;

    uint32_t qfh[4][4], qfl[4][4];
    #pragma unroll
    for (int s = 0; s < 4; ++s) {
        const uint32_t off = (uint32_t)((wq0 + arow) * AT_STRIDE + s * 16 + acol8) * 2;
        LDSM4(qfh[s][0], qfh[s][1], qfh[s][2], qfh[s][3], sQh + off);
        LDSM4(qfl[s][0], qfl[s][1], qfl[s][2], qfl[s][3], sQl + off);
    }

    float oacc[8][4];
    #pragma unroll
    for (int d = 0; d < 8; ++d)
        #pragma unroll
        for (int j = 0; j < 4; ++j) oacc[d][j] = 0.0f;
    float m0 = -1e30f, m1 = -1e30f, l0 = 0.0f, l1 = 0.0f;

    for (int kt = 0; kt < SS / 64; ++kt) {
        __syncthreads();   // previous iteration done reading K/V tiles
        {
            const size_t krow0 = (size_t)(b * SS + kt * 64);
            const __nv_bfloat16* gKh = Kh + krow0 * DD + h * DH;
            const __nv_bfloat16* gKl = Kl + krow0 * DD + h * DH;
            const __nv_bfloat16* gVh = Vh + krow0 * DD + h * DH;
            for (int f = tid; f < 512; f += 128) {
                const int r = f >> 3, c8 = (f & 7) * 8;
                const size_t go = (size_t)r * DD + c8;
                const uint32_t so = (uint32_t)(r * AT_STRIDE + c8) * 2;
                *(uint4*)(smc + 2 * AT_TILE_B + so) = *(const uint4*)(gKh + go);
                *(uint4*)(smc + 3 * AT_TILE_B + so) = *(const uint4*)(gKl + go);
                *(uint4*)(smc + 4 * AT_TILE_B + so) = *(const uint4*)(gVh + go);
            }
        }
        __syncthreads();

        // scores S[16 q][64 k] in fragments
        float sc[8][4];
        #pragma unroll
        for (int nf = 0; nf < 8; ++nf)
            #pragma unroll
            for (int j = 0; j < 4; ++j) sc[nf][j] = 0.0f;

        #pragma unroll
        for (int s = 0; s < 4; ++s) {
            uint32_t kbh[4][4], kbl[4][4];
            #pragma unroll
            for (int p = 0; p < 4; ++p) {
                const uint32_t off =
                    (uint32_t)((p * 16 + bn8 + brow) * AT_STRIDE + s * 16 + bk8) * 2;
                LDSM4(kbh[p][0], kbh[p][1], kbh[p][2], kbh[p][3], sKh + off);
                LDSM4(kbl[p][0], kbl[p][1], kbl[p][2], kbl[p][3], sKl + off);
            }
            #pragma unroll
            for (int nf = 0; nf < 8; ++nf) {
                const int p = nf >> 1, q = (nf & 1) << 1;
                MMA16816(sc[nf], qfh[s][0], qfh[s][1], qfh[s][2], qfh[s][3],
                         kbh[p][q], kbh[p][q + 1]);
                MMA16816(sc[nf], qfh[s][0], qfh[s][1], qfh[s][2], qfh[s][3],
                         kbl[p][q], kbl[p][q + 1]);
                MMA16816(sc[nf], qfl[s][0], qfl[s][1], qfl[s][2], qfl[s][3],
                         kbh[p][q], kbh[p][q + 1]);
            }
        }

        // online softmax: thread owns rows r=wq0+(lane>>2) and r+8
        float rm0 = -1e30f, rm1 = -1e30f;
        #pragma unroll
        for (int nf = 0; nf < 8; ++nf) {
            sc[nf][0] *= scale; sc[nf][1] *= scale;
            sc[nf][2] *= scale; sc[nf][3] *= scale;
            rm0 = fmaxf(rm0, fmaxf(sc[nf][0], sc[nf][1]));
            rm1 = fmaxf(rm1, fmaxf(sc[nf][2], sc[nf][3]));
        }
        rm0 = fmaxf(rm0, __shfl_xor_sync(0xffffffffu, rm0, 1));
        rm0 = fmaxf(rm0, __shfl_xor_sync(0xffffffffu, rm0, 2));
        rm1 = fmaxf(rm1, __shfl_xor_sync(0xffffffffu, rm1, 1));
        rm1 = fmaxf(rm1, __shfl_xor_sync(0xffffffffu, rm1, 2));

        const float mn0 = fmaxf(m0, rm0), mn1 = fmaxf(m1, rm1);
        const float c0 = __expf(m0 - mn0), c1 = __expf(m1 - mn1);
        float rs0 = 0.0f, rs1 = 0.0f;
        #pragma unroll
        for (int nf = 0; nf < 8; ++nf) {
            sc[nf][0] = __expf(sc[nf][0] - mn0); rs0 += sc[nf][0];
            sc[nf][1] = __expf(sc[nf][1] - mn0); rs0 += sc[nf][1];
            sc[nf][2] = __expf(sc[nf][2] - mn1); rs1 += sc[nf][2];
            sc[nf][3] = __expf(sc[nf][3] - mn1); rs1 += sc[nf][3];
        }
        rs0 += __shfl_xor_sync(0xffffffffu, rs0, 1);
        rs0 += __shfl_xor_sync(0xffffffffu, rs0, 2);
        rs1 += __shfl_xor_sync(0xffffffffu, rs1, 1);
        rs1 += __shfl_xor_sync(0xffffffffu, rs1, 2);
        l0 = l0 * c0 + rs0; l1 = l1 * c1 + rs1;
        m0 = mn0; m1 = mn1;
        #pragma unroll
        for (int d = 0; d < 8; ++d) {
            oacc[d][0] *= c0; oacc[d][1] *= c0;
            oacc[d][2] *= c1; oacc[d][3] *= c1;
        }

        // pack P (C-frag -> A-frag, in registers)
        uint32_t pa[4][4];
        #pragma unroll
        for (int s = 0; s < 4; ++s) {
            pa[s][0] = pack_bf16x2(sc[2 * s][0],     sc[2 * s][1]);
            pa[s][1] = pack_bf16x2(sc[2 * s][2],     sc[2 * s][3]);
            pa[s][2] = pack_bf16x2(sc[2 * s + 1][0], sc[2 * s + 1][1]);
            pa[s][3] = pack_bf16x2(sc[2 * s + 1][2], sc[2 * s + 1][3]);
        }

        // O += P @ V  (V B-fragments via ldmatrix.trans from [k][d] tile)
        #pragma unroll
        for (int s = 0; s < 4; ++s) {
            uint32_t vb[4][4];
            #pragma unroll
            for (int p = 0; p < 4; ++p) {
                const uint32_t off =
                    (uint32_t)((s * 16 + bk8 + brow) * AT_STRIDE + p * 16 + bn8) * 2;
                LDSM4T(vb[p][0], vb[p][1], vb[p][2], vb[p][3], sVh + off);
            }
            #pragma unroll
            for (int df = 0; df < 8; ++df) {
                const int p = df >> 1, q = (df & 1) << 1;
                MMA16816(oacc[df], pa[s][0], pa[s][1], pa[s][2], pa[s][3],
                         vb[p][q], vb[p][q + 1]);
            }
        }
    }

    // epilogue: normalize, store f32
    const float i0 = 1.0f / l0, i1 = 1.0f / l1;
    const int r0 = wq0 + (lane >> 2);
    float* o0 = Og + (qrow0 + r0) * DD + h * DH + (lane & 3) * 2;
    float* o1 = o0 + 8 * DD;
    #pragma unroll
    for (int df = 0; df < 8; ++df) {
        *(float2*)(o0 + df * 8) = make_float2(oacc[df][0] * i0, oacc[df][1] * i0);
        *(float2*)(o1 + df * 8) = make_float2(oacc[df][2] * i1, oacc[df][3] * i1);
    }
}

// ---------------------------------------------------------------------------
// Launch
// ---------------------------------------------------------------------------
extern "C" void kernel_launch(void* const* d_in, const int* in_sizes, int n_in,
                              void* d_out, int out_size)
{
    const float* x      = (const float*)d_in[0];
    const float* alpha1 = (const float*)d_in[1];
    const float* bias1  = (const float*)d_in[2];
    const float* alpha2 = (const float*)d_in[3];
    const float* bias2  = (const float*)d_in[4];
    const float* wq     = (const float*)d_in[5];
    const float* bq     = (const float*)d_in[6];
    const float* wk     = (const float*)d_in[7];
    const float* bk     = (const float*)d_in[8];
    const float* wv     = (const float*)d_in[9];
    const float* bv     = (const float*)d_in[10];
    const float* w1     = (const float*)d_in[11];
    const float* b1     = (const float*)d_in[12];
    const float* w2     = (const float*)d_in[13];
    const float* b2     = (const float*)d_in[14];
    float* out = (float*)d_out;

    float *AT, *XR;
    cudaGetSymbolAddress((void**)&AT, g_AT);
    cudaGetSymbolAddress((void**)&XR, g_XR);
    __nv_bfloat16 *X2h, *X2l, *Yh, *Yl, *Hh, *Hl;
    cudaGetSymbolAddress((void**)&X2h, g_X2h);
    cudaGetSymbolAddress((void**)&X2l, g_X2l);
    cudaGetSymbolAddress((void**)&Yh,  g_Yh);
    cudaGetSymbolAddress((void**)&Yl,  g_Yl);
    cudaGetSymbolAddress((void**)&Hh,  g_Hh);
    cudaGetSymbolAddress((void**)&Hl,  g_Hl);
    __nv_bfloat16 *Qh, *Ql, *Kh, *Kl, *Vh, *Vl;
    cudaGetSymbolAddress((void**)&Qh, g_Qh);
    cudaGetSymbolAddress((void**)&Ql, g_Ql);
    cudaGetSymbolAddress((void**)&Kh, g_Kh);
    cudaGetSymbolAddress((void**)&Kl, g_Kl);
    cudaGetSymbolAddress((void**)&Vh, g_Vh);
    cudaGetSymbolAddress((void**)&Vl, g_Vl);
    __nv_bfloat16 *Wqh, *Wql, *Wkh, *Wkl, *Wvh, *Wvl, *W1h, *W1l, *W2h, *W2l;
    cudaGetSymbolAddress((void**)&Wqh, g_Wqh);
    cudaGetSymbolAddress((void**)&Wql, g_Wql);
    cudaGetSymbolAddress((void**)&Wkh, g_Wkh);
    cudaGetSymbolAddress((void**)&Wkl, g_Wkl);
    cudaGetSymbolAddress((void**)&Wvh, g_Wvh);
    cudaGetSymbolAddress((void**)&Wvl, g_Wvl);
    cudaGetSymbolAddress((void**)&W1h, g_W1h);
    cudaGetSymbolAddress((void**)&W1l, g_W1l);
    cudaGetSymbolAddress((void**)&W2h, g_W2h);
    cudaGetSymbolAddress((void**)&W2l, g_W2l);

    cudaFuncSetAttribute(mma_gemm_kernel,
                         cudaFuncAttributeMaxDynamicSharedMemorySize, GT_SMEM);
    cudaFuncSetAttribute(mma_attn_kernel,
                         cudaFuncAttributeMaxDynamicSharedMemorySize, AT_SMEM);

    // 0. weight splits (f32 -> bf16 hi/lo)
    wsplit_kernel<<<(DD * DD / 4 + 255) / 256, 256>>>(wq, Wqh, Wql, DD * DD);
    wsplit_kernel<<<(DD * DD / 4 + 255) / 256, 256>>>(wk, Wkh, Wkl, DD * DD);
    wsplit_kernel<<<(DD * DD / 4 + 255) / 256, 256>>>(wv, Wvh, Wvl, DD * DD);
    wsplit_kernel<<<(FF * DD / 4 + 255) / 256, 256>>>(w1, W1h, W1l, FF * DD);
    wsplit_kernel<<<(DD * FF / 4 + 255) / 256, 256>>>(w2, W2h, W2l, DD * FF);

    // 1. pre-norm 1 -> split bf16
    ln_kernel<<<MM, 256>>>(x, nullptr, alpha1, bias1, nullptr, X2h, X2l, 0);

    // 2-4. Q, K, V projections -> split bf16 outputs (consumed by mma attention)
    dim3 gqkv(DD / 128, MM / 128);
    mma_gemm_kernel<<<gqkv, 256, GT_SMEM>>>(X2h, X2l, Wqh, Wql, bq, nullptr,
                                            nullptr, Qh, Ql, DD, DD, 0);
    mma_gemm_kernel<<<gqkv, 256, GT_SMEM>>>(X2h, X2l, Wkh, Wkl, bk, nullptr,
                                            nullptr, Kh, Kl, DD, DD, 0);
    mma_gemm_kernel<<<gqkv, 256, GT_SMEM>>>(X2h, X2l, Wvh, Wvl, bv, nullptr,
                                            nullptr, Vh, Vl, DD, DD, 0);

    // 5. attention (tensor cores)
    mma_attn_kernel<<<dim3(SS / 64, HH, BB), 128, AT_SMEM>>>(Qh, Ql, Kh, Kl, Vh, AT);

    // 6. residual + norm 2 + threshold -> XR (f32) + split Y
    ln_kernel<<<MM, 256>>>(x, AT, alpha2, bias2, XR, Yh, Yl, 1);

    // 7. FFN1 (relu, split bf16 out)
    mma_gemm_kernel<<<dim3(FF / 128, MM / 128), 256, GT_SMEM>>>(
        Yh, Yl, W1h, W1l, b1, nullptr, nullptr, Hh, Hl, FF, DD, 1);

    // 8. FFN2 (+bias +residual, f32 out)
    mma_gemm_kernel<<<dim3(DD / 128, MM / 128), 256, GT_SMEM>>>(
        Hh, Hl, W2h, W2l, b2, XR, out, nullptr, nullptr, DD, FF, 0);
}